// round 8
// baseline (speedup 1.0000x reference)
#include <cuda_runtime.h>
#include <math.h>

#define D4    64            // 256 dims = 64 float4
#define C     64
#define MAXNQ 4096
#define MAXNS 8192
#define QT    32            // queries per tile
#define MB    64            // members per staged chunk
#define MAXTILES (MAXNQ/QT + C)   // 192
#define NEG  (-3.0e38f)
#define SMEM_MAIN ((QT*D4 + MB*D4) * 16)   // 96 KB dynamic

// Scratch (device globals; fully rewritten every call -> replay-safe).
__device__ float g_cent[C * 256];
__device__ float g_ssum[C];
__device__ int   g_counts[C];
__device__ int   g_start[C + 1];
__device__ int   g_cidx[MAXNS];
__device__ int   g_qidx[MAXNQ];
__device__ int   g_tc[MAXTILES], g_toff[MAXTILES], g_tcnt[MAXTILES];
__device__ int   g_ntiles;

__device__ __forceinline__ float warp_sum(float v) {
#pragma unroll
    for (int o = 16; o; o >>= 1) v += __shfl_xor_sync(0xffffffffu, v, o);
    return v;
}

// Packed dual-FMA: d.lo += a.lo*b.lo ; d.hi += a.hi*b.hi   (Blackwell f32x2)
__device__ __forceinline__ void fma2(unsigned long long& d,
                                     unsigned long long a, unsigned long long b) {
    asm("fma.rn.f32x2 %0, %1, %2, %0;" : "+l"(d) : "l"(a), "l"(b));
}
__device__ __forceinline__ float hsum2(unsigned long long v) {
    float lo, hi;
    asm("mov.b64 {%0, %1}, %2;" : "=f"(lo), "=f"(hi) : "l"(v));
    return lo + hi;
}

// ---------------------------------------------------------------------------
// Kernel 1 (kPrep): single CTA, 1024 threads. ATOMIC-FREE counting sort:
// per-warp match_any histograms -> cross-warp prefix -> rank-based scatter.
// Also zeroes g_cent / g_ssum / d_out.
// ---------------------------------------------------------------------------
__global__ void __launch_bounds__(1024)
kPrep(const int* __restrict__ ys, const int* __restrict__ yq,
      int Nq, int Ns, float* __restrict__ out) {
    __shared__ int wh[32][C];      // support: per-warp counts, then bases
    __shared__ int wqh[32][C];     // queries: per-warp counts, then bases
    __shared__ int cnt[C], qcnt[C], qbase[C];
    int tid = threadIdx.x, w = tid >> 5, l = tid & 31;
    unsigned lt = (1u << l) - 1u;

    for (int i = tid; i < 32 * C; i += 1024) { (&wh[0][0])[i] = 0; (&wqh[0][0])[i] = 0; }
    for (int i = tid; i < C * 256; i += 1024) g_cent[i] = 0.0f;
    if (tid < C) g_ssum[tid] = 0.0f;
    if (tid == 0) out[0] = 0.0f;
    __syncthreads();

    int nbS = (Ns + 31) >> 5;
    int nbQ = (Nq + 31) >> 5;

    // --- per-warp histograms (leader-only RMW, no atomics) ---
    for (int bt = w; bt < nbS; bt += 32) {
        int idx = (bt << 5) + l;
        int y = (idx < Ns) ? ys[idx] : -1;
        unsigned mask = __match_any_sync(0xffffffffu, y);
        if (y >= 0 && (mask & lt) == 0) wh[w][y] += __popc(mask);
    }
    for (int bt = w; bt < nbQ; bt += 32) {
        int idx = (bt << 5) + l;
        int y = (idx < Nq) ? yq[idx] : -1;
        unsigned mask = __match_any_sync(0xffffffffu, y);
        if (y >= 0 && (mask & lt) == 0) wqh[w][y] += __popc(mask);
    }
    __syncthreads();

    // --- class totals ---
    if (tid < C) {
        int s = 0;
#pragma unroll
        for (int r = 0; r < 32; r++) s += wh[r][tid];
        cnt[tid] = s;
    } else if (tid < 2 * C) {
        int c = tid - C, s = 0;
#pragma unroll
        for (int r = 0; r < 32; r++) s += wqh[r][c];
        qcnt[c] = s;
    }
    __syncthreads();

    // --- serial schedule (tiny) ---
    if (tid == 0) {
        int acc = 0, qacc = 0, nt = 0;
        for (int c = 0; c < C; c++) {
            g_counts[c] = cnt[c]; g_start[c] = acc; acc += cnt[c];
            qbase[c] = qacc;
            for (int t = 0; t < qcnt[c]; t += QT) {
                g_tc[nt] = c; g_toff[nt] = qacc + t;
                g_tcnt[nt] = min(QT, qcnt[c] - t); nt++;
            }
            qacc += qcnt[c];
        }
        g_start[C] = acc; g_ntiles = nt;
    }
    __syncthreads();

    // --- cross-warp exclusive prefix per class: counts -> bases ---
    if (tid < C) {
        int acc = g_start[tid];
#pragma unroll
        for (int r = 0; r < 32; r++) { int t = wh[r][tid]; wh[r][tid] = acc; acc += t; }
    } else if (tid < 2 * C) {
        int c = tid - C;
        int acc = qbase[c];
#pragma unroll
        for (int r = 0; r < 32; r++) { int t = wqh[r][c]; wqh[r][c] = acc; acc += t; }
    }
    __syncthreads();

    // --- rank-based scatter (no atomics) ---
    for (int bt = w; bt < nbS; bt += 32) {
        int idx = (bt << 5) + l;
        int y = (idx < Ns) ? ys[idx] : -1;
        unsigned mask = __match_any_sync(0xffffffffu, y);
        int rank = __popc(mask & lt);
        int base = (y >= 0) ? wh[w][y] : 0;
        if (y >= 0) g_cidx[base + rank] = idx;
        __syncwarp();
        if (y >= 0 && rank == 0) wh[w][y] = base + __popc(mask);
        __syncwarp();
    }
    for (int bt = w; bt < nbQ; bt += 32) {
        int idx = (bt << 5) + l;
        int y = (idx < Nq) ? yq[idx] : -1;
        unsigned mask = __match_any_sync(0xffffffffu, y);
        int rank = __popc(mask & lt);
        int base = (y >= 0) ? wqh[w][y] : 0;
        if (y >= 0) g_qidx[base + rank] = idx;
        __syncwarp();
        if (y >= 0 && rank == 0) wqh[w][y] = base + __popc(mask);
        __syncwarp();
    }
}

// ---------------------------------------------------------------------------
// Kernel 2 (kCent): partial centroids + partial sq-norm sums.
// Grid (C, 2, 4): y = dim half, z = member quarter. atomicAdd into zeroed
// g_cent / g_ssum. 512 CTAs -> full-chip MLP for the scattered row gather.
// ---------------------------------------------------------------------------
__global__ void kCent(const float* __restrict__ xs) {
    int c = blockIdx.x, tid = threadIdx.x;
    int dim = blockIdx.y * 128 + tid;
    int s0 = g_start[c], s1 = g_start[c + 1];
    int Mc = s1 - s0;
    int b0 = s0 + (Mc * (int)blockIdx.z) / 4;
    int b1 = s0 + (Mc * ((int)blockIdx.z + 1)) / 4;
    float acc = 0.0f, acc2 = 0.0f;
    int m = b0;
    for (; m + 3 < b1; m += 4) {
        float v0 = xs[(size_t)g_cidx[m]   * 256 + dim];
        float v1 = xs[(size_t)g_cidx[m+1] * 256 + dim];
        float v2 = xs[(size_t)g_cidx[m+2] * 256 + dim];
        float v3 = xs[(size_t)g_cidx[m+3] * 256 + dim];
        acc  += (v0 + v1) + (v2 + v3);
        acc2 += (v0*v0 + v1*v1) + (v2*v2 + v3*v3);
    }
    for (; m < b1; m++) {
        float v = xs[(size_t)g_cidx[m] * 256 + dim];
        acc += v; acc2 += v * v;
    }
    atomicAdd(&g_cent[c * 256 + dim], acc);

    __shared__ float sred[128];
    sred[tid] = acc2; __syncthreads();
    for (int s = 64; s; s >>= 1) { if (tid < s) sred[tid] += sred[tid + s]; __syncthreads(); }
    if (tid == 0 && blockIdx.y == 0) atomicAdd(&g_ssum[c], sred[0]);
    if (tid == 1 && blockIdx.y == 1) atomicAdd(&g_ssum[c], sred[0]);
}

// ---------------------------------------------------------------------------
// Kernel 3 (k_main): unchanged (passing). 256 threads = 8 warps.
// Warp w owns queries 4w..4w+3; lane owns members 2l,2l+1. f32x2 accums.
// ---------------------------------------------------------------------------
__global__ void __launch_bounds__(256)
k_main(const float* __restrict__ xq, const float* __restrict__ xs,
       const int* __restrict__ pos, float* __restrict__ out, float invNq) {
    int b = blockIdx.x;
    if (b >= g_ntiles) return;

    extern __shared__ float4 dsm[];
    float4* s_q4 = dsm;                  // QT rows x 64 float4
    float4* s_m4 = dsm + QT * D4;        // MB rows x 64 float4, XOR-swizzled
    __shared__ float s_lorig[QT];
    __shared__ float s_msn[MB];
    __shared__ int   s_mj[MB];
    __shared__ float s_res[QT];

    int t = threadIdx.x, w = t >> 5, l = t & 31;
    int c    = g_tc[b];
    int qoff = g_toff[b];
    int qcnt = g_tcnt[b];
    float v  = (g_counts[c] > 1) ? -1000.0f : 0.0f;

    float qn[4]; int p[4];
#pragma unroll
    for (int k = 0; k < 4; k++) {
        int ql = 4 * w + k;
        int qi = g_qidx[qoff + min(ql, qcnt - 1)];
        const float4* src = (const float4*)xq + (size_t)qi * D4;
        float4 a = src[l], bb = src[l + 32];
        s_q4[ql * D4 + l]      = a;
        s_q4[ql * D4 + l + 32] = bb;
        float s = a.x*a.x + a.y*a.y + a.z*a.z + a.w*a.w
                + bb.x*bb.x + bb.y*bb.y + bb.z*bb.z + bb.w*bb.w;
        qn[k] = warp_sum(s);
        p[k]  = pos[qi];
    }

    int s0 = g_start[c];
    int Mc = g_start[c + 1] - s0;

    float pm[4], ps[4];
#pragma unroll
    for (int k = 0; k < 4; k++) { pm[k] = NEG; ps[k] = 0.0f; }

    const int m0 = 2 * l, m1 = 2 * l + 1;
    const int sig = l & 7;
    const ulonglong2* mr0 = (const ulonglong2*)(s_m4 + m0 * D4);
    const ulonglong2* mr1 = (const ulonglong2*)(s_m4 + m1 * D4);

    for (int base = 0; base < Mc; base += MB) {
        int nm = min(MB, Mc - base);
        __syncthreads();
        for (int r = 0; r < 8; r++) {
            int m = (r << 3) + w;
            if (m < nm) {
                int j = g_cidx[s0 + base + m];
                int sg = (m >> 1) & 7;
                const float4* src = (const float4*)xs + (size_t)j * D4;
                float4 a = src[l], bb = src[l + 32];
                s_m4[m * D4 + (l ^ sg)]        = a;
                s_m4[m * D4 + ((l + 32) ^ sg)] = bb;
                float s = a.x*a.x + a.y*a.y + a.z*a.z + a.w*a.w
                        + bb.x*bb.x + bb.y*bb.y + bb.z*bb.z + bb.w*bb.w;
                s = warp_sum(s);
                if (l == 0) { s_mj[m] = j; s_msn[m] = s; }
            } else if (l == 0) s_mj[m] = -1;
        }
        __syncthreads();

        unsigned long long acc[4][2];
#pragma unroll
        for (int k = 0; k < 4; k++) { acc[k][0] = 0ull; acc[k][1] = 0ull; }

#pragma unroll 4
        for (int d = 0; d < D4; d++) {
            int cc = d ^ sig;
            ulonglong2 A = mr0[cc];
            ulonglong2 B = mr1[cc];
#pragma unroll
            for (int k = 0; k < 4; k++) {
                ulonglong2 Q = ((const ulonglong2*)(s_q4 + (4 * w + k) * D4))[d];
                fma2(acc[k][0], Q.x, A.x);
                fma2(acc[k][0], Q.y, A.y);
                fma2(acc[k][1], Q.x, B.x);
                fma2(acc[k][1], Q.y, B.y);
            }
        }

        int   j0 = s_mj[m0],  j1 = s_mj[m1];
        float sn0 = s_msn[m0], sn1 = s_msn[m1];
#pragma unroll
        for (int k = 0; k < 4; k++) {
            float d0 = hsum2(acc[k][0]);
            float d1 = hsum2(acc[k][1]);
            float r0 = -0.5f * fmaxf(qn[k] + sn0 - 2.0f * d0, 0.0f);
            float r1 = -0.5f * fmaxf(qn[k] + sn1 - 2.0f * d1, 0.0f);
            float l0 = (j0 < 0) ? NEG : ((j0 == p[k]) ? v : r0);
            float l1 = (j1 < 0) ? NEG : ((j1 == p[k]) ? v : r1);
            if (j0 >= 0 && j0 == p[k]) s_lorig[4 * w + k] = r0;
            if (j1 >= 0 && j1 == p[k]) s_lorig[4 * w + k] = r1;
            float mx = fmaxf(pm[k], fmaxf(l0, l1));
            if (mx > -1e37f) {
                ps[k] = ps[k] * __expf(pm[k] - mx) + __expf(l0 - mx) + __expf(l1 - mx);
                pm[k] = mx;
            }
        }
    }

    float posl[4];
#pragma unroll
    for (int k = 0; k < 4; k++) {
        float m = pm[k], s = ps[k];
        for (int o = 16; o; o >>= 1) {
            float om = __shfl_xor_sync(0xffffffffu, m, o);
            float os = __shfl_xor_sync(0xffffffffu, s, o);
            float mx = fmaxf(m, om);
            if (mx > -1e37f) s = s * __expf(m - mx) + os * __expf(om - mx);
            m = mx;
        }
        posl[k] = m + __logf(s);
    }

    __syncthreads();
    for (int r = 0; r < 8; r++) {
        int m = (r << 3) + w;
        int sg = (m >> 1) & 7;
        const float4* src = (const float4*)g_cent + (size_t)m * D4;
        s_m4[m * D4 + (l ^ sg)]        = src[l];
        s_m4[m * D4 + ((l + 32) ^ sg)] = src[l + 32];
    }
    __syncthreads();

    {
        unsigned long long acc[4][2];
#pragma unroll
        for (int k = 0; k < 4; k++) { acc[k][0] = 0ull; acc[k][1] = 0ull; }

#pragma unroll 4
        for (int d = 0; d < D4; d++) {
            int cc = d ^ sig;
            ulonglong2 A = mr0[cc];
            ulonglong2 B = mr1[cc];
#pragma unroll
            for (int k = 0; k < 4; k++) {
                ulonglong2 Q = ((const ulonglong2*)(s_q4 + (4 * w + k) * D4))[d];
                fma2(acc[k][0], Q.x, A.x);
                fma2(acc[k][0], Q.y, A.y);
                fma2(acc[k][1], Q.x, B.x);
                fma2(acc[k][1], Q.y, B.y);
            }
        }

        float cnt0 = (float)g_counts[m0], cnt1 = (float)g_counts[m1];
        float ss0 = g_ssum[m0], ss1 = g_ssum[m1];
        bool  isc0 = (m0 == c), isc1 = (m1 == c);
#pragma unroll
        for (int k = 0; k < 4; k++) {
            float lo = s_lorig[4 * w + k];
            float x0 = -0.5f * (cnt0 * qn[k] + ss0) + hsum2(acc[k][0]);
            float x1 = -0.5f * (cnt1 * qn[k] + ss1) + hsum2(acc[k][1]);
            if (isc0) x0 += v - lo;
            if (isc1) x1 += v - lo;
            x0 /= cnt0 - (isc0 ? 1.0f : 0.0f);
            x1 /= cnt1 - (isc1 ? 1.0f : 0.0f);
            float m = fmaxf(x0, x1);
            float s = __expf(x0 - m) + __expf(x1 - m);
            for (int o = 16; o; o >>= 1) {
                float om = __shfl_xor_sync(0xffffffffu, m, o);
                float os = __shfl_xor_sync(0xffffffffu, s, o);
                float mx = fmaxf(m, om);
                s = s * __expf(m - mx) + os * __expf(om - mx);
                m = mx;
            }
            if (l == 0) {
                float neg = m + __logf(s);
                s_res[4 * w + k] = (4 * w + k < qcnt) ? (neg - posl[k]) * invNq : 0.0f;
            }
        }
    }

    __syncthreads();
    if (w == 0) {
        float a = s_res[l];
        a = warp_sum(a);
        if (l == 0) atomicAdd(out, a);
    }
}

extern "C" void kernel_launch(void* const* d_in, const int* in_sizes, int n_in,
                              void* d_out, int out_size) {
    const float* xq  = (const float*)d_in[0];
    const int*   yq  = (const int*)  d_in[1];
    const float* xs  = (const float*)d_in[2];
    const int*   ys  = (const int*)  d_in[3];
    const int*   pos = (const int*)  d_in[4];
    int Nq = in_sizes[1];
    int Ns = in_sizes[3];

    cudaFuncSetAttribute(k_main, cudaFuncAttributeMaxDynamicSharedMemorySize, SMEM_MAIN);

    kPrep<<<1, 1024>>>(ys, yq, Nq, Ns, (float*)d_out);
    dim3 gc(C, 2, 4);
    kCent<<<gc, 128>>>(xs);
    k_main<<<MAXTILES, 256, SMEM_MAIN>>>(xq, xs, pos, (float*)d_out, 1.0f / (float)Nq);
}

// round 9
// speedup vs baseline: 1.2605x; 1.2605x over previous
#include <cuda_runtime.h>
#include <math.h>

#define D4    64            // 256 dims = 64 float4
#define C     64
#define MAXNQ 4096
#define MAXNS 8192
#define QT    32            // queries per tile
#define MB    64            // members per staged chunk
#define MAXTILES (MAXNQ/QT + C)   // 192
#define NEG  (-3.0e38f)
#define NH   48             // histogram/scatter CTAs
#define SMEM_MAIN ((QT*D4 + MB*D4) * 16)   // 96 KB dynamic

// Scratch (device globals; fully rewritten every call -> replay-safe).
__device__ float g_cent[C * 256];
__device__ float g_ssum[C];
__device__ int   g_counts[C];
__device__ int   g_start[C + 1];
__device__ int   g_cidx[MAXNS];
__device__ int   g_qidx[MAXNQ];
__device__ int   g_tc[MAXTILES], g_toff[MAXTILES], g_tcnt[MAXTILES];
__device__ int   g_ntiles;
__device__ int   g_ph[NH][C];     // per-CTA support histograms (plain stores)
__device__ int   g_pqh[NH][C];    // per-CTA query histograms
__device__ int   g_off[C], g_qoff[C];   // scatter cursors (init by kSched)

__device__ __forceinline__ float warp_sum(float v) {
#pragma unroll
    for (int o = 16; o; o >>= 1) v += __shfl_xor_sync(0xffffffffu, v, o);
    return v;
}

// Packed dual-FMA: d.lo += a.lo*b.lo ; d.hi += a.hi*b.hi   (Blackwell f32x2)
__device__ __forceinline__ void fma2(unsigned long long& d,
                                     unsigned long long a, unsigned long long b) {
    asm("fma.rn.f32x2 %0, %1, %2, %0;" : "+l"(d) : "l"(a), "l"(b));
}
__device__ __forceinline__ float hsum2(unsigned long long v) {
    float lo, hi;
    asm("mov.b64 {%0, %1}, %2;" : "=f"(lo), "=f"(hi) : "l"(v));
    return lo + hi;
}

// ---------------------------------------------------------------------------
// Kernel 1 (kHist): 48 CTAs. Per-CTA label-slice histograms (per-warp smem,
// reduced, stored as partials — no global atomics). Also zeroes
// g_cent / g_ssum / d_out (spread across CTAs).
// ---------------------------------------------------------------------------
__global__ void kHist(const int* __restrict__ ys, const int* __restrict__ yq,
                      int Nq, int Ns, float* __restrict__ out) {
    __shared__ int h[8][C], hq[8][C];
    int tid = threadIdx.x, w = tid >> 5;
    int cta = blockIdx.x;
    for (int i = tid; i < 8 * C; i += 256) { (&h[0][0])[i] = 0; (&hq[0][0])[i] = 0; }
    __syncthreads();
    int s0 = (Ns * cta) / NH, s1 = (Ns * (cta + 1)) / NH;
    for (int j = s0 + tid; j < s1; j += 256) atomicAdd(&h[w][ys[j]], 1);
    int q0 = (Nq * cta) / NH, q1 = (Nq * (cta + 1)) / NH;
    for (int i = q0 + tid; i < q1; i += 256) atomicAdd(&hq[w][yq[i]], 1);
    __syncthreads();
    if (tid < C) {
        int s = 0;
#pragma unroll
        for (int r = 0; r < 8; r++) s += h[r][tid];
        g_ph[cta][tid] = s;
    } else if (tid < 2 * C) {
        int c = tid - C, s = 0;
#pragma unroll
        for (int r = 0; r < 8; r++) s += hq[r][c];
        g_pqh[cta][c] = s;
    }
    // zero chores (spread across the grid)
    for (int i = cta * 256 + tid; i < C * 256; i += NH * 256) g_cent[i] = 0.0f;
    if (cta == 1 && tid < C) g_ssum[tid] = 0.0f;
    if (cta == 2 && tid == 0) out[0] = 0.0f;
}

// ---------------------------------------------------------------------------
// Kernel 2 (kSched): 1 CTA. Reduce partial hists, prefix, tile schedule,
// init scatter cursors.
// ---------------------------------------------------------------------------
__global__ void kSched() {
    __shared__ int cnt[C], qcnt[C];
    int tid = threadIdx.x;
    if (tid < C) {
        int s = 0;
        for (int r = 0; r < NH; r++) s += g_ph[r][tid];
        cnt[tid] = s;
    } else if (tid < 2 * C) {
        int c = tid - C, s = 0;
        for (int r = 0; r < NH; r++) s += g_pqh[r][c];
        qcnt[c] = s;
    }
    __syncthreads();
    if (tid == 0) {
        int acc = 0, qacc = 0, nt = 0;
        for (int c = 0; c < C; c++) {
            g_counts[c] = cnt[c]; g_start[c] = acc; g_off[c] = acc; acc += cnt[c];
            g_qoff[c] = qacc;
            for (int t = 0; t < qcnt[c]; t += QT) {
                g_tc[nt] = c; g_toff[nt] = qacc + t;
                g_tcnt[nt] = min(QT, qcnt[c] - t); nt++;
            }
            qacc += qcnt[c];
        }
        g_start[C] = acc; g_ntiles = nt;
    }
}

// ---------------------------------------------------------------------------
// Kernel 3 (kScatter): 48 CTAs. Global-atomic scatter (64 L2 addresses,
// pipelined). Order within class is irrelevant downstream.
// ---------------------------------------------------------------------------
__global__ void kScatter(const int* __restrict__ ys, const int* __restrict__ yq,
                         int Nq, int Ns) {
    int tid = threadIdx.x, cta = blockIdx.x;
    int s0 = (Ns * cta) / NH, s1 = (Ns * (cta + 1)) / NH;
    for (int j = s0 + tid; j < s1; j += 256)
        g_cidx[atomicAdd(&g_off[ys[j]], 1)] = j;
    int q0 = (Nq * cta) / NH, q1 = (Nq * (cta + 1)) / NH;
    for (int i = q0 + tid; i < q1; i += 256)
        g_qidx[atomicAdd(&g_qoff[yq[i]], 1)] = i;
}

// ---------------------------------------------------------------------------
// Kernel 4 (kCent): partial centroids + partial sq-norm sums.
// Grid (C, 2, 4): y = dim half, z = member quarter. atomicAdd into zeroed
// g_cent / g_ssum.
// ---------------------------------------------------------------------------
__global__ void kCent(const float* __restrict__ xs) {
    int c = blockIdx.x, tid = threadIdx.x;
    int dim = blockIdx.y * 128 + tid;
    int s0 = g_start[c], s1 = g_start[c + 1];
    int Mc = s1 - s0;
    int b0 = s0 + (Mc * (int)blockIdx.z) / 4;
    int b1 = s0 + (Mc * ((int)blockIdx.z + 1)) / 4;
    float acc = 0.0f, acc2 = 0.0f;
    int m = b0;
    for (; m + 3 < b1; m += 4) {
        float v0 = xs[(size_t)g_cidx[m]   * 256 + dim];
        float v1 = xs[(size_t)g_cidx[m+1] * 256 + dim];
        float v2 = xs[(size_t)g_cidx[m+2] * 256 + dim];
        float v3 = xs[(size_t)g_cidx[m+3] * 256 + dim];
        acc  += (v0 + v1) + (v2 + v3);
        acc2 += (v0*v0 + v1*v1) + (v2*v2 + v3*v3);
    }
    for (; m < b1; m++) {
        float v = xs[(size_t)g_cidx[m] * 256 + dim];
        acc += v; acc2 += v * v;
    }
    atomicAdd(&g_cent[c * 256 + dim], acc);

    __shared__ float sred[128];
    sred[tid] = acc2; __syncthreads();
    for (int s = 64; s; s >>= 1) { if (tid < s) sred[tid] += sred[tid + s]; __syncthreads(); }
    if (tid == 0 && blockIdx.y == 0) atomicAdd(&g_ssum[c], sred[0]);
    if (tid == 1 && blockIdx.y == 1) atomicAdd(&g_ssum[c], sred[0]);
}

// ---------------------------------------------------------------------------
// Kernel 5 (k_main): unchanged (passing). 256 threads = 8 warps.
// Warp w owns queries 4w..4w+3; lane owns members 2l,2l+1. f32x2 accums.
// ---------------------------------------------------------------------------
__global__ void __launch_bounds__(256)
k_main(const float* __restrict__ xq, const float* __restrict__ xs,
       const int* __restrict__ pos, float* __restrict__ out, float invNq) {
    int b = blockIdx.x;
    if (b >= g_ntiles) return;

    extern __shared__ float4 dsm[];
    float4* s_q4 = dsm;                  // QT rows x 64 float4
    float4* s_m4 = dsm + QT * D4;        // MB rows x 64 float4, XOR-swizzled
    __shared__ float s_lorig[QT];
    __shared__ float s_msn[MB];
    __shared__ int   s_mj[MB];
    __shared__ float s_res[QT];

    int t = threadIdx.x, w = t >> 5, l = t & 31;
    int c    = g_tc[b];
    int qoff = g_toff[b];
    int qcnt = g_tcnt[b];
    float v  = (g_counts[c] > 1) ? -1000.0f : 0.0f;

    float qn[4]; int p[4];
#pragma unroll
    for (int k = 0; k < 4; k++) {
        int ql = 4 * w + k;
        int qi = g_qidx[qoff + min(ql, qcnt - 1)];
        const float4* src = (const float4*)xq + (size_t)qi * D4;
        float4 a = src[l], bb = src[l + 32];
        s_q4[ql * D4 + l]      = a;
        s_q4[ql * D4 + l + 32] = bb;
        float s = a.x*a.x + a.y*a.y + a.z*a.z + a.w*a.w
                + bb.x*bb.x + bb.y*bb.y + bb.z*bb.z + bb.w*bb.w;
        qn[k] = warp_sum(s);
        p[k]  = pos[qi];
    }

    int s0 = g_start[c];
    int Mc = g_start[c + 1] - s0;

    float pm[4], ps[4];
#pragma unroll
    for (int k = 0; k < 4; k++) { pm[k] = NEG; ps[k] = 0.0f; }

    const int m0 = 2 * l, m1 = 2 * l + 1;
    const int sig = l & 7;
    const ulonglong2* mr0 = (const ulonglong2*)(s_m4 + m0 * D4);
    const ulonglong2* mr1 = (const ulonglong2*)(s_m4 + m1 * D4);

    for (int base = 0; base < Mc; base += MB) {
        int nm = min(MB, Mc - base);
        __syncthreads();
        for (int r = 0; r < 8; r++) {
            int m = (r << 3) + w;
            if (m < nm) {
                int j = g_cidx[s0 + base + m];
                int sg = (m >> 1) & 7;
                const float4* src = (const float4*)xs + (size_t)j * D4;
                float4 a = src[l], bb = src[l + 32];
                s_m4[m * D4 + (l ^ sg)]        = a;
                s_m4[m * D4 + ((l + 32) ^ sg)] = bb;
                float s = a.x*a.x + a.y*a.y + a.z*a.z + a.w*a.w
                        + bb.x*bb.x + bb.y*bb.y + bb.z*bb.z + bb.w*bb.w;
                s = warp_sum(s);
                if (l == 0) { s_mj[m] = j; s_msn[m] = s; }
            } else if (l == 0) s_mj[m] = -1;
        }
        __syncthreads();

        unsigned long long acc[4][2];
#pragma unroll
        for (int k = 0; k < 4; k++) { acc[k][0] = 0ull; acc[k][1] = 0ull; }

#pragma unroll 4
        for (int d = 0; d < D4; d++) {
            int cc = d ^ sig;
            ulonglong2 A = mr0[cc];
            ulonglong2 B = mr1[cc];
#pragma unroll
            for (int k = 0; k < 4; k++) {
                ulonglong2 Q = ((const ulonglong2*)(s_q4 + (4 * w + k) * D4))[d];
                fma2(acc[k][0], Q.x, A.x);
                fma2(acc[k][0], Q.y, A.y);
                fma2(acc[k][1], Q.x, B.x);
                fma2(acc[k][1], Q.y, B.y);
            }
        }

        int   j0 = s_mj[m0],  j1 = s_mj[m1];
        float sn0 = s_msn[m0], sn1 = s_msn[m1];
#pragma unroll
        for (int k = 0; k < 4; k++) {
            float d0 = hsum2(acc[k][0]);
            float d1 = hsum2(acc[k][1]);
            float r0 = -0.5f * fmaxf(qn[k] + sn0 - 2.0f * d0, 0.0f);
            float r1 = -0.5f * fmaxf(qn[k] + sn1 - 2.0f * d1, 0.0f);
            float l0 = (j0 < 0) ? NEG : ((j0 == p[k]) ? v : r0);
            float l1 = (j1 < 0) ? NEG : ((j1 == p[k]) ? v : r1);
            if (j0 >= 0 && j0 == p[k]) s_lorig[4 * w + k] = r0;
            if (j1 >= 0 && j1 == p[k]) s_lorig[4 * w + k] = r1;
            float mx = fmaxf(pm[k], fmaxf(l0, l1));
            if (mx > -1e37f) {
                ps[k] = ps[k] * __expf(pm[k] - mx) + __expf(l0 - mx) + __expf(l1 - mx);
                pm[k] = mx;
            }
        }
    }

    float posl[4];
#pragma unroll
    for (int k = 0; k < 4; k++) {
        float m = pm[k], s = ps[k];
        for (int o = 16; o; o >>= 1) {
            float om = __shfl_xor_sync(0xffffffffu, m, o);
            float os = __shfl_xor_sync(0xffffffffu, s, o);
            float mx = fmaxf(m, om);
            if (mx > -1e37f) s = s * __expf(m - mx) + os * __expf(om - mx);
            m = mx;
        }
        posl[k] = m + __logf(s);
    }

    __syncthreads();
    for (int r = 0; r < 8; r++) {
        int m = (r << 3) + w;
        int sg = (m >> 1) & 7;
        const float4* src = (const float4*)g_cent + (size_t)m * D4;
        s_m4[m * D4 + (l ^ sg)]        = src[l];
        s_m4[m * D4 + ((l + 32) ^ sg)] = src[l + 32];
    }
    __syncthreads();

    {
        unsigned long long acc[4][2];
#pragma unroll
        for (int k = 0; k < 4; k++) { acc[k][0] = 0ull; acc[k][1] = 0ull; }

#pragma unroll 4
        for (int d = 0; d < D4; d++) {
            int cc = d ^ sig;
            ulonglong2 A = mr0[cc];
            ulonglong2 B = mr1[cc];
#pragma unroll
            for (int k = 0; k < 4; k++) {
                ulonglong2 Q = ((const ulonglong2*)(s_q4 + (4 * w + k) * D4))[d];
                fma2(acc[k][0], Q.x, A.x);
                fma2(acc[k][0], Q.y, A.y);
                fma2(acc[k][1], Q.x, B.x);
                fma2(acc[k][1], Q.y, B.y);
            }
        }

        float cnt0 = (float)g_counts[m0], cnt1 = (float)g_counts[m1];
        float ss0 = g_ssum[m0], ss1 = g_ssum[m1];
        bool  isc0 = (m0 == c), isc1 = (m1 == c);
#pragma unroll
        for (int k = 0; k < 4; k++) {
            float lo = s_lorig[4 * w + k];
            float x0 = -0.5f * (cnt0 * qn[k] + ss0) + hsum2(acc[k][0]);
            float x1 = -0.5f * (cnt1 * qn[k] + ss1) + hsum2(acc[k][1]);
            if (isc0) x0 += v - lo;
            if (isc1) x1 += v - lo;
            x0 /= cnt0 - (isc0 ? 1.0f : 0.0f);
            x1 /= cnt1 - (isc1 ? 1.0f : 0.0f);
            float m = fmaxf(x0, x1);
            float s = __expf(x0 - m) + __expf(x1 - m);
            for (int o = 16; o; o >>= 1) {
                float om = __shfl_xor_sync(0xffffffffu, m, o);
                float os = __shfl_xor_sync(0xffffffffu, s, o);
                float mx = fmaxf(m, om);
                s = s * __expf(m - mx) + os * __expf(om - mx);
                m = mx;
            }
            if (l == 0) {
                float neg = m + __logf(s);
                s_res[4 * w + k] = (4 * w + k < qcnt) ? (neg - posl[k]) * invNq : 0.0f;
            }
        }
    }

    __syncthreads();
    if (w == 0) {
        float a = s_res[l];
        a = warp_sum(a);
        if (l == 0) atomicAdd(out, a);
    }
}

extern "C" void kernel_launch(void* const* d_in, const int* in_sizes, int n_in,
                              void* d_out, int out_size) {
    const float* xq  = (const float*)d_in[0];
    const int*   yq  = (const int*)  d_in[1];
    const float* xs  = (const float*)d_in[2];
    const int*   ys  = (const int*)  d_in[3];
    const int*   pos = (const int*)  d_in[4];
    int Nq = in_sizes[1];
    int Ns = in_sizes[3];

    cudaFuncSetAttribute(k_main, cudaFuncAttributeMaxDynamicSharedMemorySize, SMEM_MAIN);

    kHist<<<NH, 256>>>(ys, yq, Nq, Ns, (float*)d_out);
    kSched<<<1, 256>>>();
    kScatter<<<NH, 256>>>(ys, yq, Nq, Ns);
    dim3 gc(C, 2, 4);
    kCent<<<gc, 128>>>(xs);
    k_main<<<MAXTILES, 256, SMEM_MAIN>>>(xq, xs, pos, (float*)d_out, 1.0f / (float)Nq);
}

// round 10
// speedup vs baseline: 1.2611x; 1.0005x over previous
#include <cuda_runtime.h>
#include <math.h>

#define D4    64            // 256 dims = 64 float4
#define C     64
#define MAXNQ 4096
#define MAXNS 8192
#define QT    32            // queries per tile
#define MB    64            // members per staged chunk
#define MAXTILES (MAXNQ/QT + C)   // 192
#define NEG  (-3.0e38f)
#define NH   48             // histogram/scatter CTAs
#define ZC   16             // kCent member splits
#define SMEM_MAIN ((QT*D4 + MB*D4) * 16)   // 96 KB dynamic

// Scratch (device globals; fully rewritten every call -> replay-safe).
__device__ float g_cent[C * 256];
__device__ float g_ssum[C];
__device__ int   g_counts[C];
__device__ int   g_start[C + 1];
__device__ int   g_cidx[MAXNS];
__device__ int   g_qidx[MAXNQ];
__device__ int   g_tc[MAXTILES], g_toff[MAXTILES], g_tcnt[MAXTILES];
__device__ int   g_ntiles;
__device__ int   g_ph[NH][C];     // per-CTA support histograms (plain stores)
__device__ int   g_pqh[NH][C];    // per-CTA query histograms
__device__ int   g_off[C], g_qoff[C];   // scatter cursors (init by kSched)

__device__ __forceinline__ float warp_sum(float v) {
#pragma unroll
    for (int o = 16; o; o >>= 1) v += __shfl_xor_sync(0xffffffffu, v, o);
    return v;
}

// Packed dual-FMA: d.lo += a.lo*b.lo ; d.hi += a.hi*b.hi   (Blackwell f32x2)
__device__ __forceinline__ void fma2(unsigned long long& d,
                                     unsigned long long a, unsigned long long b) {
    asm("fma.rn.f32x2 %0, %1, %2, %0;" : "+l"(d) : "l"(a), "l"(b));
}
__device__ __forceinline__ float hsum2(unsigned long long v) {
    float lo, hi;
    asm("mov.b64 {%0, %1}, %2;" : "=f"(lo), "=f"(hi) : "l"(v));
    return lo + hi;
}

// ---------------------------------------------------------------------------
// Kernel 1 (kHist): 48 CTAs. Per-CTA label-slice histograms (per-warp smem,
// reduced, stored as partials — no global atomics). Also zeroes
// g_cent / g_ssum / d_out (spread across CTAs).
// ---------------------------------------------------------------------------
__global__ void kHist(const int* __restrict__ ys, const int* __restrict__ yq,
                      int Nq, int Ns, float* __restrict__ out) {
    __shared__ int h[8][C], hq[8][C];
    int tid = threadIdx.x, w = tid >> 5;
    int cta = blockIdx.x;
    for (int i = tid; i < 8 * C; i += 256) { (&h[0][0])[i] = 0; (&hq[0][0])[i] = 0; }
    __syncthreads();
    int s0 = (Ns * cta) / NH, s1 = (Ns * (cta + 1)) / NH;
    for (int j = s0 + tid; j < s1; j += 256) atomicAdd(&h[w][ys[j]], 1);
    int q0 = (Nq * cta) / NH, q1 = (Nq * (cta + 1)) / NH;
    for (int i = q0 + tid; i < q1; i += 256) atomicAdd(&hq[w][yq[i]], 1);
    __syncthreads();
    if (tid < C) {
        int s = 0;
#pragma unroll
        for (int r = 0; r < 8; r++) s += h[r][tid];
        g_ph[cta][tid] = s;
    } else if (tid < 2 * C) {
        int c = tid - C, s = 0;
#pragma unroll
        for (int r = 0; r < 8; r++) s += hq[r][c];
        g_pqh[cta][c] = s;
    }
    // zero chores (spread across the grid)
    for (int i = cta * 256 + tid; i < C * 256; i += NH * 256) g_cent[i] = 0.0f;
    if (cta == 1 && tid < C) g_ssum[tid] = 0.0f;
    if (cta == 2 && tid == 0) out[0] = 0.0f;
}

// ---------------------------------------------------------------------------
// Kernel 2 (kSched): 1 CTA. Reduce partial hists, prefix, tile schedule,
// init scatter cursors.
// ---------------------------------------------------------------------------
__global__ void kSched() {
    __shared__ int cnt[C], qcnt[C];
    int tid = threadIdx.x;
    if (tid < C) {
        int s = 0;
        for (int r = 0; r < NH; r++) s += g_ph[r][tid];
        cnt[tid] = s;
    } else if (tid < 2 * C) {
        int c = tid - C, s = 0;
        for (int r = 0; r < NH; r++) s += g_pqh[r][c];
        qcnt[c] = s;
    }
    __syncthreads();
    if (tid == 0) {
        int acc = 0, qacc = 0, nt = 0;
        for (int c = 0; c < C; c++) {
            g_counts[c] = cnt[c]; g_start[c] = acc; g_off[c] = acc; acc += cnt[c];
            g_qoff[c] = qacc;
            for (int t = 0; t < qcnt[c]; t += QT) {
                g_tc[nt] = c; g_toff[nt] = qacc + t;
                g_tcnt[nt] = min(QT, qcnt[c] - t); nt++;
            }
            qacc += qcnt[c];
        }
        g_start[C] = acc; g_ntiles = nt;
    }
}

// ---------------------------------------------------------------------------
// Kernel 3 (kScatter): 48 CTAs. Global-atomic scatter (64 L2 addresses,
// pipelined). Order within class is irrelevant downstream.
// ---------------------------------------------------------------------------
__global__ void kScatter(const int* __restrict__ ys, const int* __restrict__ yq,
                         int Nq, int Ns) {
    int tid = threadIdx.x, cta = blockIdx.x;
    int s0 = (Ns * cta) / NH, s1 = (Ns * (cta + 1)) / NH;
    for (int j = s0 + tid; j < s1; j += 256)
        g_cidx[atomicAdd(&g_off[ys[j]], 1)] = j;
    int q0 = (Nq * cta) / NH, q1 = (Nq * (cta + 1)) / NH;
    for (int i = q0 + tid; i < q1; i += 256)
        g_qidx[atomicAdd(&g_qoff[yq[i]], 1)] = i;
}

// ---------------------------------------------------------------------------
// Kernel 4 (kCent): partial centroids + partial sq-norm sums.
// Grid (C, 2, ZC): y = dim half, z = member 1/ZC slice. 2048 CTAs -> high
// MLP for the scattered row gather. atomicAdd into zeroed g_cent / g_ssum.
// ---------------------------------------------------------------------------
__global__ void kCent(const float* __restrict__ xs) {
    int c = blockIdx.x, tid = threadIdx.x;
    int dim = blockIdx.y * 128 + tid;
    int s0 = g_start[c], s1 = g_start[c + 1];
    int Mc = s1 - s0;
    int b0 = s0 + (Mc * (int)blockIdx.z) / ZC;
    int b1 = s0 + (Mc * ((int)blockIdx.z + 1)) / ZC;
    float acc = 0.0f, acc2 = 0.0f;
    int m = b0;
    for (; m + 3 < b1; m += 4) {
        float v0 = xs[(size_t)g_cidx[m]   * 256 + dim];
        float v1 = xs[(size_t)g_cidx[m+1] * 256 + dim];
        float v2 = xs[(size_t)g_cidx[m+2] * 256 + dim];
        float v3 = xs[(size_t)g_cidx[m+3] * 256 + dim];
        acc  += (v0 + v1) + (v2 + v3);
        acc2 += (v0*v0 + v1*v1) + (v2*v2 + v3*v3);
    }
    for (; m < b1; m++) {
        float v = xs[(size_t)g_cidx[m] * 256 + dim];
        acc += v; acc2 += v * v;
    }
    atomicAdd(&g_cent[c * 256 + dim], acc);

    __shared__ float sred[128];
    sred[tid] = acc2; __syncthreads();
    for (int s = 64; s; s >>= 1) { if (tid < s) sred[tid] += sred[tid + s]; __syncthreads(); }
    if (tid == 0 && blockIdx.y == 0) atomicAdd(&g_ssum[c], sred[0]);
    if (tid == 1 && blockIdx.y == 1) atomicAdd(&g_ssum[c], sred[0]);
}

// ---------------------------------------------------------------------------
// Kernel 5 (k_main): unchanged (passing). 256 threads = 8 warps.
// Warp w owns queries 4w..4w+3; lane owns members 2l,2l+1. f32x2 accums.
// ---------------------------------------------------------------------------
__global__ void __launch_bounds__(256)
k_main(const float* __restrict__ xq, const float* __restrict__ xs,
       const int* __restrict__ pos, float* __restrict__ out, float invNq) {
    int b = blockIdx.x;
    if (b >= g_ntiles) return;

    extern __shared__ float4 dsm[];
    float4* s_q4 = dsm;                  // QT rows x 64 float4
    float4* s_m4 = dsm + QT * D4;        // MB rows x 64 float4, XOR-swizzled
    __shared__ float s_lorig[QT];
    __shared__ float s_msn[MB];
    __shared__ int   s_mj[MB];
    __shared__ float s_res[QT];

    int t = threadIdx.x, w = t >> 5, l = t & 31;
    int c    = g_tc[b];
    int qoff = g_toff[b];
    int qcnt = g_tcnt[b];
    float v  = (g_counts[c] > 1) ? -1000.0f : 0.0f;

    float qn[4]; int p[4];
#pragma unroll
    for (int k = 0; k < 4; k++) {
        int ql = 4 * w + k;
        int qi = g_qidx[qoff + min(ql, qcnt - 1)];
        const float4* src = (const float4*)xq + (size_t)qi * D4;
        float4 a = src[l], bb = src[l + 32];
        s_q4[ql * D4 + l]      = a;
        s_q4[ql * D4 + l + 32] = bb;
        float s = a.x*a.x + a.y*a.y + a.z*a.z + a.w*a.w
                + bb.x*bb.x + bb.y*bb.y + bb.z*bb.z + bb.w*bb.w;
        qn[k] = warp_sum(s);
        p[k]  = pos[qi];
    }

    int s0 = g_start[c];
    int Mc = g_start[c + 1] - s0;

    float pm[4], ps[4];
#pragma unroll
    for (int k = 0; k < 4; k++) { pm[k] = NEG; ps[k] = 0.0f; }

    const int m0 = 2 * l, m1 = 2 * l + 1;
    const int sig = l & 7;
    const ulonglong2* mr0 = (const ulonglong2*)(s_m4 + m0 * D4);
    const ulonglong2* mr1 = (const ulonglong2*)(s_m4 + m1 * D4);

    for (int base = 0; base < Mc; base += MB) {
        int nm = min(MB, Mc - base);
        __syncthreads();
        for (int r = 0; r < 8; r++) {
            int m = (r << 3) + w;
            if (m < nm) {
                int j = g_cidx[s0 + base + m];
                int sg = (m >> 1) & 7;
                const float4* src = (const float4*)xs + (size_t)j * D4;
                float4 a = src[l], bb = src[l + 32];
                s_m4[m * D4 + (l ^ sg)]        = a;
                s_m4[m * D4 + ((l + 32) ^ sg)] = bb;
                float s = a.x*a.x + a.y*a.y + a.z*a.z + a.w*a.w
                        + bb.x*bb.x + bb.y*bb.y + bb.z*bb.z + bb.w*bb.w;
                s = warp_sum(s);
                if (l == 0) { s_mj[m] = j; s_msn[m] = s; }
            } else if (l == 0) s_mj[m] = -1;
        }
        __syncthreads();

        unsigned long long acc[4][2];
#pragma unroll
        for (int k = 0; k < 4; k++) { acc[k][0] = 0ull; acc[k][1] = 0ull; }

#pragma unroll 4
        for (int d = 0; d < D4; d++) {
            int cc = d ^ sig;
            ulonglong2 A = mr0[cc];
            ulonglong2 B = mr1[cc];
#pragma unroll
            for (int k = 0; k < 4; k++) {
                ulonglong2 Q = ((const ulonglong2*)(s_q4 + (4 * w + k) * D4))[d];
                fma2(acc[k][0], Q.x, A.x);
                fma2(acc[k][0], Q.y, A.y);
                fma2(acc[k][1], Q.x, B.x);
                fma2(acc[k][1], Q.y, B.y);
            }
        }

        int   j0 = s_mj[m0],  j1 = s_mj[m1];
        float sn0 = s_msn[m0], sn1 = s_msn[m1];
#pragma unroll
        for (int k = 0; k < 4; k++) {
            float d0 = hsum2(acc[k][0]);
            float d1 = hsum2(acc[k][1]);
            float r0 = -0.5f * fmaxf(qn[k] + sn0 - 2.0f * d0, 0.0f);
            float r1 = -0.5f * fmaxf(qn[k] + sn1 - 2.0f * d1, 0.0f);
            float l0 = (j0 < 0) ? NEG : ((j0 == p[k]) ? v : r0);
            float l1 = (j1 < 0) ? NEG : ((j1 == p[k]) ? v : r1);
            if (j0 >= 0 && j0 == p[k]) s_lorig[4 * w + k] = r0;
            if (j1 >= 0 && j1 == p[k]) s_lorig[4 * w + k] = r1;
            float mx = fmaxf(pm[k], fmaxf(l0, l1));
            if (mx > -1e37f) {
                ps[k] = ps[k] * __expf(pm[k] - mx) + __expf(l0 - mx) + __expf(l1 - mx);
                pm[k] = mx;
            }
        }
    }

    float posl[4];
#pragma unroll
    for (int k = 0; k < 4; k++) {
        float m = pm[k], s = ps[k];
        for (int o = 16; o; o >>= 1) {
            float om = __shfl_xor_sync(0xffffffffu, m, o);
            float os = __shfl_xor_sync(0xffffffffu, s, o);
            float mx = fmaxf(m, om);
            if (mx > -1e37f) s = s * __expf(m - mx) + os * __expf(om - mx);
            m = mx;
        }
        posl[k] = m + __logf(s);
    }

    __syncthreads();
    for (int r = 0; r < 8; r++) {
        int m = (r << 3) + w;
        int sg = (m >> 1) & 7;
        const float4* src = (const float4*)g_cent + (size_t)m * D4;
        s_m4[m * D4 + (l ^ sg)]        = src[l];
        s_m4[m * D4 + ((l + 32) ^ sg)] = src[l + 32];
    }
    __syncthreads();

    {
        unsigned long long acc[4][2];
#pragma unroll
        for (int k = 0; k < 4; k++) { acc[k][0] = 0ull; acc[k][1] = 0ull; }

#pragma unroll 4
        for (int d = 0; d < D4; d++) {
            int cc = d ^ sig;
            ulonglong2 A = mr0[cc];
            ulonglong2 B = mr1[cc];
#pragma unroll
            for (int k = 0; k < 4; k++) {
                ulonglong2 Q = ((const ulonglong2*)(s_q4 + (4 * w + k) * D4))[d];
                fma2(acc[k][0], Q.x, A.x);
                fma2(acc[k][0], Q.y, A.y);
                fma2(acc[k][1], Q.x, B.x);
                fma2(acc[k][1], Q.y, B.y);
            }
        }

        float cnt0 = (float)g_counts[m0], cnt1 = (float)g_counts[m1];
        float ss0 = g_ssum[m0], ss1 = g_ssum[m1];
        bool  isc0 = (m0 == c), isc1 = (m1 == c);
#pragma unroll
        for (int k = 0; k < 4; k++) {
            float lo = s_lorig[4 * w + k];
            float x0 = -0.5f * (cnt0 * qn[k] + ss0) + hsum2(acc[k][0]);
            float x1 = -0.5f * (cnt1 * qn[k] + ss1) + hsum2(acc[k][1]);
            if (isc0) x0 += v - lo;
            if (isc1) x1 += v - lo;
            x0 /= cnt0 - (isc0 ? 1.0f : 0.0f);
            x1 /= cnt1 - (isc1 ? 1.0f : 0.0f);
            float m = fmaxf(x0, x1);
            float s = __expf(x0 - m) + __expf(x1 - m);
            for (int o = 16; o; o >>= 1) {
                float om = __shfl_xor_sync(0xffffffffu, m, o);
                float os = __shfl_xor_sync(0xffffffffu, s, o);
                float mx = fmaxf(m, om);
                s = s * __expf(m - mx) + os * __expf(om - mx);
                m = mx;
            }
            if (l == 0) {
                float neg = m + __logf(s);
                s_res[4 * w + k] = (4 * w + k < qcnt) ? (neg - posl[k]) * invNq : 0.0f;
            }
        }
    }

    __syncthreads();
    if (w == 0) {
        float a = s_res[l];
        a = warp_sum(a);
        if (l == 0) atomicAdd(out, a);
    }
}

extern "C" void kernel_launch(void* const* d_in, const int* in_sizes, int n_in,
                              void* d_out, int out_size) {
    const float* xq  = (const float*)d_in[0];
    const int*   yq  = (const int*)  d_in[1];
    const float* xs  = (const float*)d_in[2];
    const int*   ys  = (const int*)  d_in[3];
    const int*   pos = (const int*)  d_in[4];
    int Nq = in_sizes[1];
    int Ns = in_sizes[3];

    cudaFuncSetAttribute(k_main, cudaFuncAttributeMaxDynamicSharedMemorySize, SMEM_MAIN);

    kHist<<<NH, 256>>>(ys, yq, Nq, Ns, (float*)d_out);
    kSched<<<1, 256>>>();
    kScatter<<<NH, 256>>>(ys, yq, Nq, Ns);
    dim3 gc(C, 2, ZC);
    kCent<<<gc, 128>>>(xs);
    k_main<<<MAXTILES, 256, SMEM_MAIN>>>(xq, xs, pos, (float*)d_out, 1.0f / (float)Nq);
}